// round 15
// baseline (speedup 1.0000x reference)
#include <cuda_runtime.h>
#include <cstdint>

// YOLO loss "slim5": R10 body (grid-stride, no smem, no barriers, x[20] in
// regs, 3 CTAs/SM) + prefetch.global.L2 of iteration i+2's pred/target rows.
// Rows are 120B vs 128B lines, so one per-lane prefetch covers every line of
// the warp's span — later demand loads (scalars AND obj rows) hit L2.

#define THREADS   256
#define NPART_MAX 2048

__device__ float        g_part[6][NPART_MAX];
__device__ unsigned int g_count = 0;

__device__ __forceinline__ void prefetch_l2(const void* p)
{
    asm volatile("prefetch.global.L2 [%0];" :: "l"(p));
}

__device__ __forceinline__ void block_reduce6(float* vals, float* s_red, int tid)
{
    #pragma unroll
    for (int v = 0; v < 6; v++) {
        #pragma unroll
        for (int off = 16; off > 0; off >>= 1)
            vals[v] += __shfl_down_sync(0xffffffffu, vals[v], off);
    }
    const int warp = tid >> 5;
    const int lane = tid & 31;
    if (lane == 0) {
        #pragma unroll
        for (int v = 0; v < 6; v++) s_red[warp * 6 + v] = vals[v];
    }
    __syncthreads();
    if (tid == 0) {
        #pragma unroll
        for (int v = 0; v < 6; v++) {
            float s = 0.f;
            #pragma unroll
            for (int w2 = 0; w2 < THREADS / 32; w2++) s += s_red[w2 * 6 + v];
            vals[v] = s;
        }
    }
}

__global__ __launch_bounds__(THREADS, 3)
void yolo_slim5(const float* __restrict__ pred,
                const float* __restrict__ target,
                const int*   __restrict__ choice,
                float*       __restrict__ out,
                int n_cells)
{
    __shared__ float s_red[(THREADS / 32) * 6];
    __shared__ bool  s_last;

    const int tid = threadIdx.x;
    float acc[6] = {0.f, 0.f, 0.f, 0.f, 0.f, 0.f};

    const long long stride = (long long)gridDim.x * THREADS;

    for (long long cell = (long long)blockIdx.x * THREADS + tid;
         cell < n_cells; cell += stride)
    {
        // ---- L2 prefetch for iteration i+2 (covers all lines of the span) ----
        {
            long long pf = cell + 2 * stride;
            if (pf < n_cells) {
                prefetch_l2(pred   + pf * 30);
                prefetch_l2(target + pf * 30);
                prefetch_l2(choice + pf);
            }
        }

        const float* p = pred   + cell * 30;
        const float* t = target + cell * 30;

        // always-needed scalars (5 independent loads -> MLP)
        const float t4 = t[4];
        const int   cv = choice[cell];
        const float p4 = p[4];
        const float p9 = p[9];
        const float t9 = t[9];

        if (t4 > 0.f) {
            // ---- obj cell (~10%): rows now L1/L2-resident ----
            const bool c = cv != 0;
            const int  o = c ? 0 : 5;
            acc[4] += 1.f;

            float dx = p[o + 0] - t[o + 0];
            float dy = p[o + 1] - t[o + 1];
            float dw = p[o + 2] - sqrtf(t[o + 2]);
            float dh = p[o + 3] - sqrtf(t[o + 3]);
            acc[0] += 0.5f * (dx * dx + dy * dy) + 0.5f * (dw * dw + dh * dh);

            float pobj = c ? p4 : p9;
            float tobj = c ? t4 : t9;
            float d = pobj - tobj;
            acc[2] += d * d;

            // class logits: 10 aligned float2 loads (byte 40 within 120B row)
            float x[20];
            const float2* pc2 = (const float2*)(p + 10);
            #pragma unroll
            for (int k = 0; k < 10; k++) {
                float2 v = pc2[k];
                x[2 * k]     = v.x;
                x[2 * k + 1] = v.y;
            }
            float mx = -1e30f;
            #pragma unroll
            for (int k = 0; k < 20; k++) mx = fmaxf(mx, x[k]);
            float den = 0.f;
            #pragma unroll
            for (int k = 0; k < 20; k++) den += __expf(x[k] - mx);
            float inv = __fdividef(1.f, den);
            // den2 = sum exp(sm_k); sm in [0,1] -> shiftless LSE safe
            float den2 = 0.f;
            #pragma unroll
            for (int k = 0; k < 20; k++) den2 += __expf(__expf(x[k] - mx) * inv);
            float lse2 = __logf(den2);

            // argmax over target classes (first max), carrying matching logit
            const float2* tc2 = (const float2*)(t + 10);
            float bm = -1e30f, xsel = 0.f;
            #pragma unroll
            for (int k = 0; k < 10; k++) {
                float2 v = tc2[k];
                if (v.x > bm) { bm = v.x; xsel = x[2 * k]; }
                if (v.y > bm) { bm = v.y; xsel = x[2 * k + 1]; }
            }
            float smsel = __expf(xsel - mx) * inv;
            acc[1] += lse2 - smsel;
        } else {
            // ---- noobj cell: uses only already-loaded scalars ----
            acc[5] += 1.f;
            float d0 = p4 - t4;
            float d1 = p9 - t9;
            acc[3] += d0 * d0 + d1 * d1;
        }
    }

    __syncthreads();
    block_reduce6(acc, s_red, tid);

    if (tid == 0) {
        #pragma unroll
        for (int v = 0; v < 6; v++) g_part[v][blockIdx.x] = acc[v];
        __threadfence();
        unsigned int ticket = atomicAdd(&g_count, 1u);
        s_last = (ticket == gridDim.x - 1);
    }
    __syncthreads();

    if (s_last) {
        __threadfence();
        const int npart = gridDim.x;
        float a[6] = {0.f, 0.f, 0.f, 0.f, 0.f, 0.f};
        for (int i = tid; i < npart; i += THREADS) {
            #pragma unroll
            for (int v = 0; v < 6; v++) a[v] += g_part[v][i];
        }
        __syncthreads();
        block_reduce6(a, s_red, tid);
        if (tid == 0) {
            float n_obj = fmaxf(a[4], 1.f);
            float n_no  = fmaxf(a[5], 1.f);
            out[0] = 5.0f * a[0];          // loc_loss
            out[1] = a[1] / n_obj;         // cls_loss
            out[2] = a[2];                 // obj_loss
            out[3] = 0.5f * a[3] / n_no;   // noobj_loss
            g_count = 0;                   // reset for next graph replay
        }
    }
}

extern "C" void kernel_launch(void* const* d_in, const int* in_sizes, int n_in,
                              void* d_out, int out_size)
{
    const float* pred   = (const float*)d_in[0];
    const float* target = (const float*)d_in[1];
    const int*   choice = (const int*)d_in[2];
    float* out = (float*)d_out;

    const int n_cells = in_sizes[2];

    int grid = 3 * 148;                      // 3 CTAs/SM x 256 thr (regs ~80)
    long long want = ((long long)n_cells + THREADS - 1) / THREADS;
    if ((long long)grid > want) grid = (int)want;
    if (grid < 1) grid = 1;
    if (grid > NPART_MAX) grid = NPART_MAX;

    yolo_slim5<<<grid, THREADS>>>(pred, target, choice, out, n_cells);
}

// round 17
// speedup vs baseline: 1.3632x; 1.3632x over previous
#include <cuda_runtime.h>
#include <cstdint>

// YOLO loss "slim6": R10 body verbatim (grid-stride, no smem staging, no
// barriers, 3 CTAs/SM). Host picks a grid whose thread count divides n_cells
// exactly -> every thread runs the same iteration count, no straggler tail.

#define THREADS   256
#define NPART_MAX 2048

__device__ float        g_part[6][NPART_MAX];
__device__ unsigned int g_count = 0;

__device__ __forceinline__ void block_reduce6(float* vals, float* s_red, int tid)
{
    #pragma unroll
    for (int v = 0; v < 6; v++) {
        #pragma unroll
        for (int off = 16; off > 0; off >>= 1)
            vals[v] += __shfl_down_sync(0xffffffffu, vals[v], off);
    }
    const int warp = tid >> 5;
    const int lane = tid & 31;
    if (lane == 0) {
        #pragma unroll
        for (int v = 0; v < 6; v++) s_red[warp * 6 + v] = vals[v];
    }
    __syncthreads();
    if (tid == 0) {
        #pragma unroll
        for (int v = 0; v < 6; v++) {
            float s = 0.f;
            #pragma unroll
            for (int w2 = 0; w2 < THREADS / 32; w2++) s += s_red[w2 * 6 + v];
            vals[v] = s;
        }
    }
}

__global__ __launch_bounds__(THREADS, 3)
void yolo_slim6(const float* __restrict__ pred,
                const float* __restrict__ target,
                const int*   __restrict__ choice,
                float*       __restrict__ out,
                int n_cells)
{
    __shared__ float s_red[(THREADS / 32) * 6];
    __shared__ bool  s_last;

    const int tid = threadIdx.x;
    float acc[6] = {0.f, 0.f, 0.f, 0.f, 0.f, 0.f};

    const long long stride = (long long)gridDim.x * THREADS;

    for (long long cell = (long long)blockIdx.x * THREADS + tid;
         cell < n_cells; cell += stride)
    {
        const float* p = pred   + cell * 30;
        const float* t = target + cell * 30;

        // always-needed scalars (5 independent loads -> MLP)
        const float t4 = t[4];
        const int   cv = choice[cell];
        const float p4 = p[4];
        const float p9 = p[9];
        const float t9 = t[9];

        if (t4 > 0.f) {
            // ---- obj cell (~10%): fetch rows (mostly cached lines) ----
            const bool c = cv != 0;
            const int  o = c ? 0 : 5;
            acc[4] += 1.f;

            float dx = p[o + 0] - t[o + 0];
            float dy = p[o + 1] - t[o + 1];
            float dw = p[o + 2] - sqrtf(t[o + 2]);
            float dh = p[o + 3] - sqrtf(t[o + 3]);
            acc[0] += 0.5f * (dx * dx + dy * dy) + 0.5f * (dw * dw + dh * dh);

            float pobj = c ? p4 : p9;
            float tobj = c ? t4 : t9;
            float d = pobj - tobj;
            acc[2] += d * d;

            // class logits: 10 aligned float2 loads (byte 40 within 120B row)
            float x[20];
            const float2* pc2 = (const float2*)(p + 10);
            #pragma unroll
            for (int k = 0; k < 10; k++) {
                float2 v = pc2[k];
                x[2 * k]     = v.x;
                x[2 * k + 1] = v.y;
            }
            float mx = -1e30f;
            #pragma unroll
            for (int k = 0; k < 20; k++) mx = fmaxf(mx, x[k]);
            float den = 0.f;
            #pragma unroll
            for (int k = 0; k < 20; k++) den += __expf(x[k] - mx);
            float inv = __fdividef(1.f, den);
            // den2 = sum exp(sm_k); sm in [0,1] -> shiftless LSE safe
            float den2 = 0.f;
            #pragma unroll
            for (int k = 0; k < 20; k++) den2 += __expf(__expf(x[k] - mx) * inv);
            float lse2 = __logf(den2);

            // argmax over target classes (first max), carrying matching logit
            const float2* tc2 = (const float2*)(t + 10);
            float bm = -1e30f, xsel = 0.f;
            #pragma unroll
            for (int k = 0; k < 10; k++) {
                float2 v = tc2[k];
                if (v.x > bm) { bm = v.x; xsel = x[2 * k]; }
                if (v.y > bm) { bm = v.y; xsel = x[2 * k + 1]; }
            }
            float smsel = __expf(xsel - mx) * inv;
            acc[1] += lse2 - smsel;
        } else {
            // ---- noobj cell: uses only already-loaded scalars ----
            acc[5] += 1.f;
            float d0 = p4 - t4;
            float d1 = p9 - t9;
            acc[3] += d0 * d0 + d1 * d1;
        }
    }

    __syncthreads();
    block_reduce6(acc, s_red, tid);

    if (tid == 0) {
        #pragma unroll
        for (int v = 0; v < 6; v++) g_part[v][blockIdx.x] = acc[v];
        __threadfence();
        unsigned int ticket = atomicAdd(&g_count, 1u);
        s_last = (ticket == gridDim.x - 1);
    }
    __syncthreads();

    if (s_last) {
        __threadfence();
        const int npart = gridDim.x;
        float a[6] = {0.f, 0.f, 0.f, 0.f, 0.f, 0.f};
        for (int i = tid; i < npart; i += THREADS) {
            #pragma unroll
            for (int v = 0; v < 6; v++) a[v] += g_part[v][i];
        }
        __syncthreads();
        block_reduce6(a, s_red, tid);
        if (tid == 0) {
            float n_obj = fmaxf(a[4], 1.f);
            float n_no  = fmaxf(a[5], 1.f);
            out[0] = 5.0f * a[0];          // loc_loss
            out[1] = a[1] / n_obj;         // cls_loss
            out[2] = a[2];                 // obj_loss
            out[3] = 0.5f * a[3] / n_no;   // noobj_loss
            g_count = 0;                   // reset for next graph replay
        }
    }
}

extern "C" void kernel_launch(void* const* d_in, const int* in_sizes, int n_in,
                              void* d_out, int out_size)
{
    const float* pred   = (const float*)d_in[0];
    const float* target = (const float*)d_in[1];
    const int*   choice = (const int*)d_in[2];
    float* out = (float*)d_out;

    const int n_cells = in_sizes[2];

    // One wave at 3 CTAs/SM is <= 444 CTAs. Prefer the largest grid <= 444
    // whose thread count divides n_cells exactly (balanced: every thread runs
    // the same number of iterations). Fall back to 444 if none divides.
    int grid = 444;
    for (int g = 444; g >= 296; g--) {           // >= 2 CTAs/SM keeps parallelism
        if (n_cells % (g * THREADS) == 0) { grid = g; break; }
    }
    long long want = ((long long)n_cells + THREADS - 1) / THREADS;
    if ((long long)grid > want) grid = (int)want;
    if (grid < 1) grid = 1;
    if (grid > NPART_MAX) grid = NPART_MAX;

    yolo_slim6<<<grid, THREADS>>>(pred, target, choice, out, n_cells);
}